// round 10
// baseline (speedup 1.0000x reference)
#include <cuda_runtime.h>
#include <cuda_fp16.h>
#include <math.h>
#include <stdint.h>

// ---------------- problem dims ----------------
constexpr int kB = 4, kS = 2048, kD = 512, kH = 8, kDH = 64;
constexpr int kMLP = 2048, kBLK = 128, kNB = 16, kL = 4;
constexpr int kBS = kB * kS;                 // 8192 rows
constexpr int kBSD = kBS * kD;               // 4,194,304

// ---------------- scratch (static device globals; no allocation) ----------------
static __device__ float g_x[kBSD];
static __device__ __align__(256) __half g_qh[kBSD];
static __device__ __align__(256) __half g_kh[kBSD];
static __device__ __align__(256) __half g_vh[kBSD];
static __device__ __align__(256) __half g_skh[kBSD];
static __device__ __align__(256) __half g_svh[kBSD];
static __device__ __align__(256) __half g_hh[kBSD];          // LN outputs (fp16)
static __device__ __align__(256) __half g_oh[kBSD];          // attention out (fp16)
static __device__ __align__(256) __half g_mlph[kBS * kMLP];  // gelu out (fp16)
static __device__ __align__(256) __half g_wq_h[kL * kD * kD];
static __device__ __align__(256) __half g_wk_h[kL * kD * kD];
static __device__ __align__(256) __half g_wv_h[kL * kD * kD];
static __device__ __align__(256) __half g_wo_h[kL * kD * kD];
static __device__ __align__(256) __half g_w1_h[kL * kD * kMLP];
static __device__ __align__(256) __half g_w2_h[kL * kMLP * kD];
static __device__ float g_ksum[kB * kNB * kD];
static __device__ float g_perm[kB * kH * kNB * kNB];
static __device__ float g_smask[kB * kH * kNB * kBLK];

// ---------------- fp32 -> fp16 bulk convert (all 6 weights, 1 launch) ----------------
__global__ void f2h6_kernel(const float* __restrict__ s0, const float* __restrict__ s1,
                            const float* __restrict__ s2, const float* __restrict__ s3,
                            const float* __restrict__ s4, const float* __restrict__ s5,
                            __half* __restrict__ d0, __half* __restrict__ d1,
                            __half* __restrict__ d2, __half* __restrict__ d3,
                            __half* __restrict__ d4, __half* __restrict__ d5,
                            int nW, int nM) {
    int seg = blockIdx.y;
    int n = (seg < 4) ? nW : nM;
    int i = (blockIdx.x * 256 + threadIdx.x) * 4;
    if (i >= n) return;
    const float* s; __half* d;
    switch (seg) {
        case 0: s = s0; d = d0; break;
        case 1: s = s1; d = d1; break;
        case 2: s = s2; d = d2; break;
        case 3: s = s3; d = d3; break;
        case 4: s = s4; d = d4; break;
        default: s = s5; d = d5; break;
    }
    float4 f = *(const float4*)(s + i);
    __half2* dp = (__half2*)(d + i);
    dp[0] = __floats2half2_rn(f.x, f.y);
    dp[1] = __floats2half2_rn(f.z, f.w);
}

// ---------------- embed + positional encoding ----------------
__global__ void embed_pe_kernel(const int* __restrict__ tokens,
                                const float* __restrict__ embed,
                                float* __restrict__ x) {
    int idx = blockIdx.x * 256 + threadIdx.x;
    if (idx >= kBSD) return;
    int d = idx & (kD - 1);
    int bs = idx >> 9;
    int s = bs & (kS - 1);
    int tok = tokens[bs];
    int i2 = (d >> 1) * 2;
    float freq = expf(-(float)i2 * (logf(10000.0f) / (float)kD));
    float ang = (float)s * freq;
    float pe = (d & 1) ? cosf(ang) : sinf(ang);
    x[idx] = embed[tok * kD + d] + pe;
}

// ---------------- layernorm: fp32 in, fp16 out (or fp32 for final) ----------------
__global__ __launch_bounds__(128) void ln_kernel(const float* __restrict__ x,
                                                 const float* __restrict__ sc,
                                                 const float* __restrict__ bi,
                                                 __half* __restrict__ outh,
                                                 float* __restrict__ outf) {
    int row = blockIdx.x;
    const float* xp = x + (size_t)row * kD;
    float v[4];
    float s = 0.f, ss = 0.f;
#pragma unroll
    for (int i = 0; i < 4; i++) {
        v[i] = xp[threadIdx.x + i * 128];
        s += v[i];
        ss += v[i] * v[i];
    }
#pragma unroll
    for (int o = 16; o >= 1; o >>= 1) {
        s += __shfl_down_sync(0xffffffffu, s, o);
        ss += __shfl_down_sync(0xffffffffu, ss, o);
    }
    __shared__ float sa[4], sb[4];
    int w = threadIdx.x >> 5;
    if ((threadIdx.x & 31) == 0) { sa[w] = s; sb[w] = ss; }
    __syncthreads();
    s = sa[0] + sa[1] + sa[2] + sa[3];
    ss = sb[0] + sb[1] + sb[2] + sb[3];
    float mean = s * (1.0f / kD);
    float var = ss * (1.0f / kD) - mean * mean;
    float r = rsqrtf(var + 1e-6f);
#pragma unroll
    for (int i = 0; i < 4; i++) {
        int d = threadIdx.x + i * 128;
        float o = (v[i] - mean) * r * sc[d] + bi[d];
        if (outh) outh[(size_t)row * kD + d] = __float2half_rn(o);
        else outf[(size_t)row * kD + d] = o;
    }
}

// ---------------- mma helpers ----------------
__device__ __forceinline__ float gelu_f(float x) {
    const float c = 0.7978845608028654f;
    float x3 = x * x * x;
    return 0.5f * x * (1.0f + tanhf(c * (x + 0.044715f * x3)));
}
__device__ __forceinline__ uint32_t smem_u32(const void* p) {
    return (uint32_t)__cvta_generic_to_shared(p);
}
__device__ __forceinline__ void ldsm_x4(uint32_t& r0, uint32_t& r1, uint32_t& r2,
                                        uint32_t& r3, uint32_t addr) {
    asm volatile("ldmatrix.sync.aligned.m8n8.x4.shared.b16 {%0,%1,%2,%3},[%4];"
                 : "=r"(r0), "=r"(r1), "=r"(r2), "=r"(r3) : "r"(addr));
}
__device__ __forceinline__ void ldsm_x4t(uint32_t& r0, uint32_t& r1, uint32_t& r2,
                                         uint32_t& r3, uint32_t addr) {
    asm volatile("ldmatrix.sync.aligned.m8n8.x4.trans.shared.b16 {%0,%1,%2,%3},[%4];"
                 : "=r"(r0), "=r"(r1), "=r"(r2), "=r"(r3) : "r"(addr));
}
__device__ __forceinline__ void mma_f16(float* c, uint32_t a0, uint32_t a1,
                                        uint32_t a2, uint32_t a3,
                                        uint32_t b0, uint32_t b1) {
    asm volatile(
        "mma.sync.aligned.m16n8k16.row.col.f32.f16.f16.f32 "
        "{%0,%1,%2,%3},{%4,%5,%6,%7},{%8,%9},{%0,%1,%2,%3};"
        : "+f"(c[0]), "+f"(c[1]), "+f"(c[2]), "+f"(c[3])
        : "r"(a0), "r"(a1), "r"(a2), "r"(a3), "r"(b0), "r"(b1));
}
__device__ __forceinline__ void cp16(uint32_t dst, const void* src) {
    asm volatile("cp.async.cg.shared.global [%0],[%1],16;" :: "r"(dst), "l"(src));
}
__device__ __forceinline__ uint32_t pack_h2(float a, float b) {
    __half2 h = __floats2half2_rn(a, b);
    return *(uint32_t*)&h;
}

// ---------------- fp16 tensor-core GEMM (4-stage, 4 warps, 64x64 warp tiles) ----------------
constexpr int kStages = 4;
constexpr int kBM = 128, kBN = 128, kBKg = 32;
constexpr int kAP = 40, kBP = 136;
constexpr int kASTG = kBM * kAP;
constexpr int kBSTG = kBKg * kBP;
constexpr int kSmemHalves = kStages * (kASTG + kBSTG);
constexpr int kSmemBytes = kSmemHalves * 2;

// epi 0: Ch = alpha*acc (fp16)
// epi 1: Ch = gelu(acc + bias) (fp16)
// epi 2: Cf = resid + acc + (bias? bias : 0) (fp32)
__global__ __launch_bounds__(128, 2) void hgemm_kernel(
    int M, int N, int K, float alpha,
    const __half* __restrict__ A, const __half* __restrict__ Bm,
    const float* __restrict__ bias, const float* __restrict__ resid,
    float* __restrict__ Cf, __half* __restrict__ Ch, int epi) {
    extern __shared__ __half smem[];
    __half* As = smem;
    __half* Bs = smem + kStages * kASTG;

    int tid = threadIdx.x, lane = tid & 31, w = tid >> 5;
    int wr = w >> 1, wc = w & 1;       // 2x2 warp grid, warp tile 64x64
    int br = blockIdx.y, bc = blockIdx.x;
    const __half* Ap = A + (size_t)br * kBM * K;
    const __half* Bp = Bm + (size_t)bc * kBN;

    float acc[4][8][4];
#pragma unroll
    for (int i = 0; i < 4; i++)
#pragma unroll
        for (int j = 0; j < 8; j++)
#pragma unroll
            for (int r = 0; r < 4; r++) acc[i][j][r] = 0.f;

    auto issue = [&](int stage, int k0) {
        uint32_t ab = smem_u32(As + stage * kASTG);
        uint32_t bb = smem_u32(Bs + stage * kBSTG);
#pragma unroll
        for (int p = 0; p < 4; p++) {
            int id = tid + p * 128;
            int ar = id >> 2, ac = id & 3;          // A: 128 rows x 4 chunks
            cp16(ab + (uint32_t)(ar * kAP + ac * 8) * 2, Ap + (size_t)ar * K + k0 + ac * 8);
            int brr = id >> 4, bcc = id & 15;       // B: 32 rows x 16 chunks
            cp16(bb + (uint32_t)(brr * kBP + bcc * 8) * 2,
                 Bp + (size_t)(k0 + brr) * N + bcc * 8);
        }
        asm volatile("cp.async.commit_group;");
    };

    int nt = K / kBKg;
#pragma unroll
    for (int t = 0; t < kStages - 1; t++) issue(t, t * kBKg);

    int rowoff = (lane & 7) + ((lane >> 3) & 1) * 8;
    int seloff = (lane >> 4) * 8;

    for (int t = 0; t < nt; t++) {
        asm volatile("cp.async.wait_group %0;" :: "n"(kStages - 2));
        __syncthreads();
        int tn = t + kStages - 1;
        if (tn < nt) issue(tn % kStages, tn * kBKg);
        int buf = t % kStages;
        const __half* Ab = As + buf * kASTG;
        const __half* Bb = Bs + buf * kBSTG;
#pragma unroll
        for (int s = 0; s < 2; s++) {
            int k0 = s * 16;
            uint32_t af[4][4], bf[8][2];
#pragma unroll
            for (int i = 0; i < 4; i++) {
                int m0 = wr * 64 + i * 16;
                uint32_t addr = smem_u32(Ab + (m0 + rowoff) * kAP + k0 + seloff);
                ldsm_x4(af[i][0], af[i][1], af[i][2], af[i][3], addr);
            }
#pragma unroll
            for (int j2 = 0; j2 < 4; j2++) {
                int n0 = wc * 64 + j2 * 16;
                uint32_t addr = smem_u32(Bb + (k0 + rowoff) * kBP + n0 + seloff);
                uint32_t r0, r1, r2, r3;
                ldsm_x4t(r0, r1, r2, r3, addr);
                bf[j2 * 2][0] = r0; bf[j2 * 2][1] = r1;
                bf[j2 * 2 + 1][0] = r2; bf[j2 * 2 + 1][1] = r3;
            }
#pragma unroll
            for (int i = 0; i < 4; i++)
#pragma unroll
                for (int j = 0; j < 8; j++)
                    mma_f16(acc[i][j], af[i][0], af[i][1], af[i][2], af[i][3],
                            bf[j][0], bf[j][1]);
        }
    }

    int lq = lane >> 2, lr = lane & 3;
#pragma unroll
    for (int i = 0; i < 4; i++) {
        int r0 = br * kBM + wr * 64 + i * 16 + lq;
#pragma unroll
        for (int j = 0; j < 8; j++) {
            int col = bc * kBN + wc * 64 + j * 8 + lr * 2;
#pragma unroll
            for (int half = 0; half < 2; half++) {
                int row = r0 + half * 8;
                float v0 = acc[i][j][half * 2 + 0];
                float v1 = acc[i][j][half * 2 + 1];
                if (epi == 0) {
                    *(__half2*)(Ch + (size_t)row * N + col) =
                        __floats2half2_rn(v0 * alpha, v1 * alpha);
                } else if (epi == 1) {
                    v0 = gelu_f(v0 + bias[col]);
                    v1 = gelu_f(v1 + bias[col + 1]);
                    *(__half2*)(Ch + (size_t)row * N + col) = __floats2half2_rn(v0, v1);
                } else {
                    const float* rp = resid + (size_t)row * N + col;
                    float2 rr = *(const float2*)rp;
                    v0 += rr.x; v1 += rr.y;
                    if (bias) { v0 += bias[col]; v1 += bias[col + 1]; }
                    *(float2*)(Cf + (size_t)row * N + col) = make_float2(v0, v1);
                }
            }
        }
    }
}

// ---------------- ksum (fp16 in, fp32 out) ----------------
__global__ __launch_bounds__(512) void ksum_kernel(const __half* __restrict__ k,
                                                   float* __restrict__ ksum) {
    int bn = blockIdx.x;
    int tid = threadIdx.x;
    const __half* base = k + (size_t)bn * kBLK * kD + tid;
    float s = 0.f;
#pragma unroll 8
    for (int c = 0; c < kBLK; c++) s += __half2float(base[(size_t)c * kD]);
    ksum[bn * kD + tid] = s;
}

// ---------------- sinkhorn ----------------
__global__ __launch_bounds__(256) void sinkhorn_kernel(const float* __restrict__ ksum,
                                                       const float* __restrict__ sw,
                                                       const int* __restrict__ tokens,
                                                       float* __restrict__ perm_out,
                                                       float* __restrict__ smask_out) {
    int b = blockIdx.x / kH, h = blockIdx.x % kH;
    int tid = threadIdx.x;
    int n = tid >> 4, m = tid & 15;
    const float* kp = ksum + ((size_t)(b * kNB + n)) * kD + h * kDH;
    const float* wp = sw + (size_t)h * kDH * kNB + m;
    float la = 0.f;
#pragma unroll
    for (int d = 0; d < kDH; d++) la += kp[d] * wp[d * kNB];

    __shared__ float sm[16][17];
    for (int it = 0; it < 8; it++) {
        float mx = la;
#pragma unroll
        for (int o = 8; o >= 1; o >>= 1)
            mx = fmaxf(mx, __shfl_xor_sync(0xffffffffu, mx, o, 16));
        float e = expf(la - mx);
        float sum = e;
#pragma unroll
        for (int o = 8; o >= 1; o >>= 1)
            sum += __shfl_xor_sync(0xffffffffu, sum, o, 16);
        la = la - (mx + logf(sum));
        sm[n][m] = la;
        __syncthreads();
        float cmx = -1e30f;
#pragma unroll
        for (int i = 0; i < 16; i++) cmx = fmaxf(cmx, sm[i][m]);
        float cs = 0.f;
#pragma unroll
        for (int i = 0; i < 16; i++) cs += expf(sm[i][m] - cmx);
        la = la - (cmx + logf(cs));
        __syncthreads();
    }
    float p = expf(la);
    sm[n][m] = p;
    perm_out[((size_t)(b * kH + h) * kNB + n) * kNB + m] = p;
    __syncthreads();
    for (int idx = tid; idx < kNB * kBLK; idx += 256) {
        int nn = idx >> 7, c = idx & 127;
        float s = 0.f;
#pragma unroll
        for (int mm = 0; mm < 16; mm++) {
            float mb = (tokens[b * kS + mm * kBLK + c] > 0) ? 1.f : 0.f;
            s += sm[nn][mm] * mb;
        }
        smask_out[((size_t)(b * kH + h) * kNB + nn) * kBLK + c] = (s > 0.5f) ? 1.f : 0.f;
    }
}

// ---------------- sort-mix (fp16 in/out, fp32 accumulate) ----------------
__global__ __launch_bounds__(256) void sortmix_kernel(const float* __restrict__ perm,
                                                      const __half* __restrict__ k,
                                                      const __half* __restrict__ v,
                                                      __half* __restrict__ sk,
                                                      __half* __restrict__ sv) {
    int chunk = blockIdx.x;
    int h = blockIdx.y;
    int b = blockIdx.z;
    __shared__ float P[16][16];
    __shared__ float T[16][512];
    int tid = threadIdx.x;
    P[tid >> 4][tid & 15] = perm[(size_t)(b * kH + h) * 256 + tid];
    int cd0 = chunk * 512;

    for (int phase = 0; phase < 2; phase++) {
        const __half* src = phase ? v : k;
        __half* dst = phase ? sv : sk;
        __syncthreads();
        for (int idx = tid; idx < 16 * 512; idx += 256) {
            int m = idx >> 9;
            int j = idx & 511;
            int cd = cd0 + j;
            int c = cd >> 6, d = cd & 63;
            T[m][j] = __half2float(src[((size_t)(b * kS + m * kBLK + c)) * kD + h * kDH + d]);
        }
        __syncthreads();
        for (int idx = tid; idx < 16 * 512; idx += 256) {
            int n = idx >> 9;
            int j = idx & 511;
            float acc = 0.f;
#pragma unroll
            for (int m = 0; m < 16; m++) acc += P[n][m] * T[m][j];
            int cd = cd0 + j;
            int c = cd >> 6, d = cd & 63;
            dst[((size_t)(b * kS + n * kBLK + c)) * kD + h * kDH + d] = __float2half_rn(acc);
        }
    }
}

// ---------------- attention: mma.sync flash-style ----------------
constexpr int kAPitch = 72;
constexpr int kAttnQ = 128 * kAPitch;
constexpr int kAttnKV = 256 * kAPitch;
constexpr int kAttnSmem = (kAttnQ + 2 * kAttnKV) * 2 + 256 * 4 + 16;

__global__ __launch_bounds__(256, 1) void attn_kernel(
    const __half* __restrict__ q, const __half* __restrict__ k,
    const __half* __restrict__ v, const __half* __restrict__ sk,
    const __half* __restrict__ sv, const float* __restrict__ smask,
    const int* __restrict__ tokens, __half* __restrict__ o) {
    extern __shared__ char asm_raw[];
    __half* QS = (__half*)asm_raw;
    __half* KS = QS + kAttnQ;
    __half* VS = KS + kAttnKV;
    float* biasS = (float*)(VS + kAttnKV);

    int n0 = blockIdx.x, h = blockIdx.y, b = blockIdx.z;
    int tid = threadIdx.x, lane = tid & 31, wid = tid >> 5;

    uint32_t qb = smem_u32(QS), kb = smem_u32(KS), vb = smem_u32(VS);
    for (int id = tid; id < 1024; id += 256) {
        int row = id >> 3, ch = id & 7;
        cp16(qb + (uint32_t)row * 144 + ch * 16,
             q + ((size_t)(b * kS + n0 * 128 + row)) * kD + h * 64 + ch * 8);
    }
    for (int id = tid; id < 2048; id += 256) {
        int row = id >> 3, ch = id & 7;
        const __half* src = (row < 128)
            ? k + ((size_t)(b * kS + n0 * 128 + row)) * kD + h * 64 + ch * 8
            : sk + ((size_t)(b * kS + n0 * 128 + row - 128)) * kD + h * 64 + ch * 8;
        cp16(kb + (uint32_t)row * 144 + ch * 16, src);
    }
    for (int id = tid; id < 2048; id += 256) {
        int row = id >> 3, ch = id & 7;
        const __half* src = (row < 128)
            ? v + ((size_t)(b * kS + n0 * 128 + row)) * kD + h * 64 + ch * 8
            : sv + ((size_t)(b * kS + n0 * 128 + row - 128)) * kD + h * 64 + ch * 8;
        cp16(vb + (uint32_t)row * 144 + ch * 16, src);
    }
    asm volatile("cp.async.commit_group;");
    for (int j = tid; j < 256; j += 256) {
        float mv;
        if (j < 128) mv = (tokens[b * kS + n0 * kBLK + j] > 0) ? 1.f : 0.f;
        else mv = smask[((size_t)(b * kH + h) * kNB + n0) * kBLK + (j - 128)];
        biasS[j] = (mv > 0.5f) ? 0.f : -1e9f;
    }
    asm volatile("cp.async.wait_group 0;");
    __syncthreads();

    int r0w = wid * 16;
    int rowoff = (lane & 7) + ((lane >> 3) & 1) * 8;
    int seloff = (lane >> 4) * 8;
    int browoff = (lane & 7) + ((lane >> 4) & 1) * 8;
    int bseloff = ((lane >> 3) & 1) * 8;

    uint32_t aq[4][4];
#pragma unroll
    for (int ks = 0; ks < 4; ks++) {
        uint32_t addr = smem_u32(QS + (r0w + rowoff) * kAPitch + ks * 16 + seloff);
        ldsm_x4(aq[ks][0], aq[ks][1], aq[ks][2], aq[ks][3], addr);
    }

    float sacc[16][8];
#pragma unroll
    for (int nt = 0; nt < 16; nt++)
#pragma unroll
        for (int c = 0; c < 8; c++) sacc[nt][c] = 0.f;

#pragma unroll
    for (int nt = 0; nt < 16; nt++) {
#pragma unroll
        for (int ks = 0; ks < 4; ks++) {
            uint32_t r0, r1, r2, r3;
            uint32_t addr = smem_u32(KS + (nt * 16 + browoff) * kAPitch + ks * 16 + bseloff);
            ldsm_x4(r0, r1, r2, r3, addr);
            mma_f16(&sacc[nt][0], aq[ks][0], aq[ks][1], aq[ks][2], aq[ks][3], r0, r1);
            mma_f16(&sacc[nt][4], aq[ks][0], aq[ks][1], aq[ks][2], aq[ks][3], r2, r3);
        }
    }

    int colbase = (lane & 3) * 2;
    float m0 = -1e30f, m1 = -1e30f;
#pragma unroll
    for (int nt = 0; nt < 16; nt++) {
#pragma unroll
        for (int sub = 0; sub < 2; sub++) {
            float2 bb = *(float2*)&biasS[nt * 16 + sub * 8 + colbase];
            sacc[nt][sub * 4 + 0] += bb.x;
            sacc[nt][sub * 4 + 1] += bb.y;
            sacc[nt][sub * 4 + 2] += bb.x;
            sacc[nt][sub * 4 + 3] += bb.y;
            m0 = fmaxf(m0, fmaxf(sacc[nt][sub * 4 + 0], sacc[nt][sub * 4 + 1]));
            m1 = fmaxf(m1, fmaxf(sacc[nt][sub * 4 + 2], sacc[nt][sub * 4 + 3]));
        }
    }
    m0 = fmaxf(m0, __shfl_xor_sync(0xffffffffu, m0, 1));
    m0 = fmaxf(m0, __shfl_xor_sync(0xffffffffu, m0, 2));
    m1 = fmaxf(m1, __shfl_xor_sync(0xffffffffu, m1, 1));
    m1 = fmaxf(m1, __shfl_xor_sync(0xffffffffu, m1, 2));
    float l0 = 0.f, l1 = 0.f;
#pragma unroll
    for (int nt = 0; nt < 16; nt++) {
#pragma unroll
        for (int sub = 0; sub < 2; sub++) {
            float p0 = __expf(sacc[nt][sub * 4 + 0] - m0);
            float p1 = __expf(sacc[nt][sub * 4 + 1] - m0);
            float p2 = __expf(sacc[nt][sub * 4 + 2] - m1);
            float p3 = __expf(sacc[nt][sub * 4 + 3] - m1);
            sacc[nt][sub * 4 + 0] = p0; sacc[nt][sub * 4 + 1] = p1;
            sacc[nt][sub * 4 + 2] = p2; sacc[nt][sub * 4 + 3] = p3;
            l0 += p0 + p1; l1 += p2 + p3;
        }
    }
    l0 += __shfl_xor_sync(0xffffffffu, l0, 1);
    l0 += __shfl_xor_sync(0xffffffffu, l0, 2);
    l1 += __shfl_xor_sync(0xffffffffu, l1, 1);
    l1 += __shfl_xor_sync(0xffffffffu, l1, 2);

    float oacc[8][4];
#pragma unroll
    for (int i = 0; i < 8; i++)
#pragma unroll
        for (int c = 0; c < 4; c++) oacc[i][c] = 0.f;

#pragma unroll
    for (int kt = 0; kt < 16; kt++) {
        uint32_t pa0 = pack_h2(sacc[kt][0], sacc[kt][1]);
        uint32_t pa1 = pack_h2(sacc[kt][2], sacc[kt][3]);
        uint32_t pa2 = pack_h2(sacc[kt][4], sacc[kt][5]);
        uint32_t pa3 = pack_h2(sacc[kt][6], sacc[kt][7]);
#pragma unroll
        for (int dg = 0; dg < 4; dg++) {
            uint32_t r0, r1, r2, r3;
            uint32_t addr = smem_u32(VS + (kt * 16 + rowoff) * kAPitch + dg * 16 + seloff);
            ldsm_x4t(r0, r1, r2, r3, addr);
            mma_f16(oacc[dg * 2], pa0, pa1, pa2, pa3, r0, r1);
            mma_f16(oacc[dg * 2 + 1], pa0, pa1, pa2, pa3, r2, r3);
        }
    }

    float inv0 = 1.f / l0, inv1 = 1.f / l1;
    int row0 = n0 * 128 + r0w + (lane >> 2);
#pragma unroll
    for (int dsub = 0; dsub < 8; dsub++) {
        int col = h * 64 + dsub * 8 + colbase;
        *(__half2*)(o + ((size_t)(b * kS + row0)) * kD + col) =
            __floats2half2_rn(oacc[dsub][0] * inv0, oacc[dsub][1] * inv0);
        *(__half2*)(o + ((size_t)(b * kS + row0 + 8)) * kD + col) =
            __floats2half2_rn(oacc[dsub][2] * inv1, oacc[dsub][3] * inv1);
    }
}

// ---------------- host orchestration ----------------
extern "C" void kernel_launch(void* const* d_in, const int* in_sizes, int n_in,
                              void* d_out, int out_size) {
    const int* tokens = (const int*)d_in[0];
    const float* embed = (const float*)d_in[1];
    const float* ln1_s = (const float*)d_in[2];
    const float* ln1_b = (const float*)d_in[3];
    const float* wq = (const float*)d_in[4];
    const float* wk = (const float*)d_in[5];
    const float* wv = (const float*)d_in[6];
    const float* wo = (const float*)d_in[7];
    const float* sortw = (const float*)d_in[8];
    const float* ln2_s = (const float*)d_in[9];
    const float* ln2_b = (const float*)d_in[10];
    const float* w1 = (const float*)d_in[11];
    const float* b1 = (const float*)d_in[12];
    const float* w2 = (const float*)d_in[13];
    const float* b2 = (const float*)d_in[14];
    const float* lnf_s = (const float*)d_in[15];
    const float* lnf_b = (const float*)d_in[16];
    float* out = (float*)d_out;

    float *x, *ksum, *perm, *smask;
    __half *qh, *kh, *vh, *skh, *svh, *hh, *oh, *mlph, *wqh, *wkh, *wvh, *woh, *w1h, *w2h;
    cudaGetSymbolAddress((void**)&x, g_x);
    cudaGetSymbolAddress((void**)&qh, g_qh);
    cudaGetSymbolAddress((void**)&kh, g_kh);
    cudaGetSymbolAddress((void**)&vh, g_vh);
    cudaGetSymbolAddress((void**)&skh, g_skh);
    cudaGetSymbolAddress((void**)&svh, g_svh);
    cudaGetSymbolAddress((void**)&ksum, g_ksum);
    cudaGetSymbolAddress((void**)&perm, g_perm);
    cudaGetSymbolAddress((void**)&smask, g_smask);
    cudaGetSymbolAddress((void**)&hh, g_hh);
    cudaGetSymbolAddress((void**)&oh, g_oh);
    cudaGetSymbolAddress((void**)&mlph, g_mlph);
    cudaGetSymbolAddress((void**)&wqh, g_wq_h);
    cudaGetSymbolAddress((void**)&wkh, g_wk_h);
    cudaGetSymbolAddress((void**)&wvh, g_wv_h);
    cudaGetSymbolAddress((void**)&woh, g_wo_h);
    cudaGetSymbolAddress((void**)&w1h, g_w1_h);
    cudaGetSymbolAddress((void**)&w2h, g_w2_h);

    cudaFuncSetAttribute(hgemm_kernel, cudaFuncAttributeMaxDynamicSharedMemorySize,
                         kSmemBytes);
    cudaFuncSetAttribute(attn_kernel, cudaFuncAttributeMaxDynamicSharedMemorySize,
                         kAttnSmem);

    int nW = kL * kD * kD;
    int nM = kL * kD * kMLP;
    {
        dim3 g(nM / 4 / 256, 6);
        f2h6_kernel<<<g, 256>>>(wq, wk, wv, wo, w1, w2,
                                wqh, wkh, wvh, woh, w1h, w2h, nW, nM);
    }

    embed_pe_kernel<<<(kBSD + 255) / 256, 256>>>(tokens, embed, x);

    const float qscale = 1.0f / 8.0f;
    dim3 gD(kD / 128, kBS / 128);
    dim3 gM(kMLP / 128, kBS / 128);

    for (int l = 0; l < kL; l++) {
        __half* wq_l = wqh + (size_t)l * kD * kD;
        __half* wk_l = wkh + (size_t)l * kD * kD;
        __half* wv_l = wvh + (size_t)l * kD * kD;
        __half* wo_l = woh + (size_t)l * kD * kD;
        const float* sw_l = sortw + (size_t)l * kH * kDH * kNB;
        __half* w1_l = w1h + (size_t)l * kD * kMLP;
        const float* b1_l = b1 + (size_t)l * kMLP;
        __half* w2_l = w2h + (size_t)l * kMLP * kD;
        const float* b2_l = b2 + (size_t)l * kD;

        ln_kernel<<<kBS, 128>>>(x, ln1_s + l * kD, ln1_b + l * kD, hh, nullptr);
        hgemm_kernel<<<gD, 128, kSmemBytes>>>(kBS, kD, kD, qscale, hh, wq_l, nullptr, nullptr, nullptr, qh, 0);
        hgemm_kernel<<<gD, 128, kSmemBytes>>>(kBS, kD, kD, 1.0f, hh, wk_l, nullptr, nullptr, nullptr, kh, 0);
        hgemm_kernel<<<gD, 128, kSmemBytes>>>(kBS, kD, kD, 1.0f, hh, wv_l, nullptr, nullptr, nullptr, vh, 0);

        ksum_kernel<<<kB * kNB, 512>>>(kh, ksum);
        sinkhorn_kernel<<<kB * kH, 256>>>(ksum, sw_l, tokens, perm, smask);
        sortmix_kernel<<<dim3(16, kH, kB), 256>>>(perm, kh, vh, skh, svh);

        attn_kernel<<<dim3(kNB, kH, kB), 256, kAttnSmem>>>(qh, kh, vh, skh, svh,
                                                           smask, tokens, oh);

        // x = x + o @ wo
        hgemm_kernel<<<gD, 128, kSmemBytes>>>(kBS, kD, kD, 1.0f, oh, wo_l, nullptr, x, x, nullptr, 2);

        // MLP
        ln_kernel<<<kBS, 128>>>(x, ln2_s + l * kD, ln2_b + l * kD, hh, nullptr);
        hgemm_kernel<<<gM, 128, kSmemBytes>>>(kBS, kMLP, kD, 1.0f, hh, w1_l, b1_l, nullptr, nullptr, mlph, 1);
        hgemm_kernel<<<gD, 128, kSmemBytes>>>(kBS, kD, kMLP, 1.0f, mlph, w2_l, b2_l, x, x, nullptr, 2);
    }

    ln_kernel<<<kBS, 128>>>(x, lnf_s, lnf_b, nullptr, out);
}

// round 11
// speedup vs baseline: 1.0581x; 1.0581x over previous
#include <cuda_runtime.h>
#include <cuda_fp16.h>
#include <math.h>
#include <stdint.h>

// ---------------- problem dims ----------------
constexpr int kB = 4, kS = 2048, kD = 512, kH = 8, kDH = 64;
constexpr int kMLP = 2048, kBLK = 128, kNB = 16, kL = 4;
constexpr int kBS = kB * kS;                 // 8192 rows
constexpr int kBSD = kBS * kD;               // 4,194,304
constexpr int kQKV = 3 * kD;                 // 1536

// ---------------- scratch (static device globals; no allocation) ----------------
static __device__ float g_x[kBSD];
static __device__ __align__(256) __half g_qh[kBSD];
static __device__ __align__(256) __half g_kh[kBSD];
static __device__ __align__(256) __half g_vh[kBSD];
static __device__ __align__(256) __half g_skh[kBSD];
static __device__ __align__(256) __half g_svh[kBSD];
static __device__ __align__(256) __half g_hh[kBSD];          // LN outputs (fp16)
static __device__ __align__(256) __half g_oh[kBSD];          // attention out (fp16)
static __device__ __align__(256) __half g_mlph[kBS * kMLP];  // gelu out (fp16)
static __device__ __align__(256) __half g_wqkv[kL * kD * kQKV]; // [l][k][qkv-col]
static __device__ __align__(256) __half g_wo_h[kL * kD * kD];
static __device__ __align__(256) __half g_w1_h[kL * kD * kMLP];
static __device__ __align__(256) __half g_w2_h[kL * kMLP * kD];
static __device__ float g_ksum[kB * kNB * kD];
static __device__ float g_perm[kB * kH * kNB * kNB];
static __device__ float g_smask[kB * kH * kNB * kBLK];

// ---------------- fp32 -> fp16 weight conversion (6 segments, 1 launch) ----------------
// seg 0/1/2: wq(x1/8)/wk/wv -> wqkv concat; seg 3: wo; seg 4: w1; seg 5: w2
__global__ void wconv_kernel(const float* __restrict__ s0, const float* __restrict__ s1,
                             const float* __restrict__ s2, const float* __restrict__ s3,
                             const float* __restrict__ s4, const float* __restrict__ s5,
                             __half* __restrict__ dqkv, __half* __restrict__ d3,
                             __half* __restrict__ d4, __half* __restrict__ d5,
                             int nW, int nM) {
    int seg = blockIdx.y;
    int n = (seg < 4) ? nW : nM;
    int i = (blockIdx.x * 256 + threadIdx.x) * 4;
    if (i >= n) return;
    const float* s;
    float scale = 1.0f;
    switch (seg) {
        case 0: s = s0; scale = 0.125f; break;
        case 1: s = s1; break;
        case 2: s = s2; break;
        case 3: s = s3; break;
        case 4: s = s4; break;
        default: s = s5; break;
    }
    float4 f = *(const float4*)(s + i);
    f.x *= scale; f.y *= scale; f.z *= scale; f.w *= scale;
    __half2 h0 = __floats2half2_rn(f.x, f.y);
    __half2 h1 = __floats2half2_rn(f.z, f.w);
    if (seg < 3) {
        // src idx i -> l, row, col ; dst = l*512*1536 + row*1536 + seg*512 + col
        int l = i >> 18;                 // / (512*512)
        int rem = i & ((1 << 18) - 1);
        int row = rem >> 9, col = rem & 511;
        __half2* dp = (__half2*)(dqkv + (size_t)l * kD * kQKV + (size_t)row * kQKV +
                                 seg * kD + col);
        dp[0] = h0; dp[1] = h1;
    } else {
        __half* d = (seg == 3) ? d3 : (seg == 4) ? d4 : d5;
        __half2* dp = (__half2*)(d + i);
        dp[0] = h0; dp[1] = h1;
    }
}

// ---------------- embed + positional encoding ----------------
__global__ void embed_pe_kernel(const int* __restrict__ tokens,
                                const float* __restrict__ embed,
                                float* __restrict__ x) {
    int idx = blockIdx.x * 256 + threadIdx.x;
    if (idx >= kBSD) return;
    int d = idx & (kD - 1);
    int bs = idx >> 9;
    int s = bs & (kS - 1);
    int tok = tokens[bs];
    int i2 = (d >> 1) * 2;
    float freq = expf(-(float)i2 * (logf(10000.0f) / (float)kD));
    float ang = (float)s * freq;
    float pe = (d & 1) ? cosf(ang) : sinf(ang);
    x[idx] = embed[tok * kD + d] + pe;
}

// ---------------- layernorm: fp32 in, fp16 out (or fp32 for final) ----------------
__global__ __launch_bounds__(128) void ln_kernel(const float* __restrict__ x,
                                                 const float* __restrict__ sc,
                                                 const float* __restrict__ bi,
                                                 __half* __restrict__ outh,
                                                 float* __restrict__ outf) {
    int row = blockIdx.x;
    const float* xp = x + (size_t)row * kD;
    float v[4];
    float s = 0.f, ss = 0.f;
#pragma unroll
    for (int i = 0; i < 4; i++) {
        v[i] = xp[threadIdx.x + i * 128];
        s += v[i];
        ss += v[i] * v[i];
    }
#pragma unroll
    for (int o = 16; o >= 1; o >>= 1) {
        s += __shfl_down_sync(0xffffffffu, s, o);
        ss += __shfl_down_sync(0xffffffffu, ss, o);
    }
    __shared__ float sa[4], sb[4];
    int w = threadIdx.x >> 5;
    if ((threadIdx.x & 31) == 0) { sa[w] = s; sb[w] = ss; }
    __syncthreads();
    s = sa[0] + sa[1] + sa[2] + sa[3];
    ss = sb[0] + sb[1] + sb[2] + sb[3];
    float mean = s * (1.0f / kD);
    float var = ss * (1.0f / kD) - mean * mean;
    float r = rsqrtf(var + 1e-6f);
#pragma unroll
    for (int i = 0; i < 4; i++) {
        int d = threadIdx.x + i * 128;
        float o = (v[i] - mean) * r * sc[d] + bi[d];
        if (outh) outh[(size_t)row * kD + d] = __float2half_rn(o);
        else outf[(size_t)row * kD + d] = o;
    }
}

// ---------------- mma helpers ----------------
__device__ __forceinline__ float gelu_f(float x) {
    const float c = 0.7978845608028654f;
    float x3 = x * x * x;
    return 0.5f * x * (1.0f + tanhf(c * (x + 0.044715f * x3)));
}
__device__ __forceinline__ uint32_t smem_u32(const void* p) {
    return (uint32_t)__cvta_generic_to_shared(p);
}
__device__ __forceinline__ void ldsm_x4(uint32_t& r0, uint32_t& r1, uint32_t& r2,
                                        uint32_t& r3, uint32_t addr) {
    asm volatile("ldmatrix.sync.aligned.m8n8.x4.shared.b16 {%0,%1,%2,%3},[%4];"
                 : "=r"(r0), "=r"(r1), "=r"(r2), "=r"(r3) : "r"(addr));
}
__device__ __forceinline__ void ldsm_x4t(uint32_t& r0, uint32_t& r1, uint32_t& r2,
                                         uint32_t& r3, uint32_t addr) {
    asm volatile("ldmatrix.sync.aligned.m8n8.x4.trans.shared.b16 {%0,%1,%2,%3},[%4];"
                 : "=r"(r0), "=r"(r1), "=r"(r2), "=r"(r3) : "r"(addr));
}
__device__ __forceinline__ void mma_f16(float* c, uint32_t a0, uint32_t a1,
                                        uint32_t a2, uint32_t a3,
                                        uint32_t b0, uint32_t b1) {
    asm volatile(
        "mma.sync.aligned.m16n8k16.row.col.f32.f16.f16.f32 "
        "{%0,%1,%2,%3},{%4,%5,%6,%7},{%8,%9},{%0,%1,%2,%3};"
        : "+f"(c[0]), "+f"(c[1]), "+f"(c[2]), "+f"(c[3])
        : "r"(a0), "r"(a1), "r"(a2), "r"(a3), "r"(b0), "r"(b1));
}
__device__ __forceinline__ void cp16(uint32_t dst, const void* src) {
    asm volatile("cp.async.cg.shared.global [%0],[%1],16;" :: "r"(dst), "l"(src));
}
__device__ __forceinline__ uint32_t pack_h2(float a, float b) {
    __half2 h = __floats2half2_rn(a, b);
    return *(uint32_t*)&h;
}

// ---------------- fp16 tensor-core GEMM (4-stage, 8 warps, 64x32 warp tiles) ----------------
constexpr int kStages = 4;
constexpr int kBM = 128, kBN = 128, kBKg = 32;
constexpr int kAP = 40, kBP = 136;
constexpr int kASTG = kBM * kAP;
constexpr int kBSTG = kBKg * kBP;
constexpr int kSmemHalves = kStages * (kASTG + kBSTG);
constexpr int kSmemBytes = kSmemHalves * 2;

// epi 0: QKV triple-output fp16 (Nout=512 each; segment by bc>>2)
// epi 1: Ch = gelu(acc + bias) (fp16)
// epi 2: Cf = resid + acc + (bias? bias : 0) (fp32)
__global__ __launch_bounds__(256, 2) void hgemm_kernel(
    int M, int N, int K,
    const __half* __restrict__ A, const __half* __restrict__ Bm,
    const float* __restrict__ bias, const float* __restrict__ resid,
    float* __restrict__ Cf, __half* __restrict__ Ch,
    __half* __restrict__ Chk, __half* __restrict__ Chv, int epi) {
    extern __shared__ __half smem[];
    __half* As = smem;
    __half* Bs = smem + kStages * kASTG;

    int tid = threadIdx.x, lane = tid & 31, w = tid >> 5;
    int wr = w >> 2, wc = w & 3;       // 2x4 warp grid, warp tile 64x32
    int br = blockIdx.y, bc = blockIdx.x;
    const __half* Ap = A + (size_t)br * kBM * K;
    const __half* Bp = Bm + (size_t)bc * kBN;

    float acc[4][4][4];
#pragma unroll
    for (int i = 0; i < 4; i++)
#pragma unroll
        for (int j = 0; j < 4; j++)
#pragma unroll
            for (int r = 0; r < 4; r++) acc[i][j][r] = 0.f;

    int arow = tid >> 2, achk = tid & 3;
    int brow = tid >> 4, bchk = tid & 15;

    auto issue = [&](int stage, int k0) {
        uint32_t ab = smem_u32(As + stage * kASTG);
        uint32_t bb = smem_u32(Bs + stage * kBSTG);
#pragma unroll
        for (int p = 0; p < 2; p++) {
            int r = arow + p * 64;
            cp16(ab + (uint32_t)(r * kAP + achk * 8) * 2, Ap + (size_t)r * K + k0 + achk * 8);
        }
#pragma unroll
        for (int p = 0; p < 2; p++) {
            int r = brow + p * 16;
            cp16(bb + (uint32_t)(r * kBP + bchk * 8) * 2, Bp + (size_t)(k0 + r) * N + bchk * 8);
        }
        asm volatile("cp.async.commit_group;");
    };

    int nt = K / kBKg;
#pragma unroll
    for (int t = 0; t < kStages - 1; t++) issue(t, t * kBKg);

    int rowoff = (lane & 7) + ((lane >> 3) & 1) * 8;
    int seloff = (lane >> 4) * 8;

    for (int t = 0; t < nt; t++) {
        asm volatile("cp.async.wait_group %0;" :: "n"(kStages - 2));
        __syncthreads();
        int tn = t + kStages - 1;
        if (tn < nt) issue(tn % kStages, tn * kBKg);
        int buf = t % kStages;
        const __half* Ab = As + buf * kASTG;
        const __half* Bb = Bs + buf * kBSTG;

        // software-pipelined 2 k-slices: prefetch slice s+1 frags during slice s MMAs
        uint32_t af[2][4][4], bf[2][4][2];
        auto load_frags = [&](int s) {
            int k0 = s * 16;
#pragma unroll
            for (int i = 0; i < 4; i++) {
                int m0 = wr * 64 + i * 16;
                uint32_t addr = smem_u32(Ab + (m0 + rowoff) * kAP + k0 + seloff);
                ldsm_x4(af[s][i][0], af[s][i][1], af[s][i][2], af[s][i][3], addr);
            }
#pragma unroll
            for (int j2 = 0; j2 < 2; j2++) {
                int n0 = wc * 32 + j2 * 16;
                uint32_t addr = smem_u32(Bb + (k0 + rowoff) * kBP + n0 + seloff);
                uint32_t r0, r1, r2, r3;
                ldsm_x4t(r0, r1, r2, r3, addr);
                bf[s][j2 * 2][0] = r0; bf[s][j2 * 2][1] = r1;
                bf[s][j2 * 2 + 1][0] = r2; bf[s][j2 * 2 + 1][1] = r3;
            }
        };
        load_frags(0);
        load_frags(1);
#pragma unroll
        for (int s = 0; s < 2; s++) {
#pragma unroll
            for (int i = 0; i < 4; i++)
#pragma unroll
                for (int j = 0; j < 4; j++)
                    mma_f16(acc[i][j], af[s][i][0], af[s][i][1], af[s][i][2], af[s][i][3],
                            bf[s][j][0], bf[s][j][1]);
        }
    }

    int lq = lane >> 2, lr = lane & 3;
    // QKV segment dispatch (epi 0 only)
    __half* dsel = Ch;
    int colshift = 0;
    if (epi == 0) {
        int seg = bc >> 2;                 // 128-col blocks: 0-3 q, 4-7 k, 8-11 v
        dsel = (seg == 0) ? Ch : (seg == 1) ? Chk : Chv;
        colshift = seg * 512;
    }
#pragma unroll
    for (int i = 0; i < 4; i++) {
        int r0 = br * kBM + wr * 64 + i * 16 + lq;
#pragma unroll
        for (int j = 0; j < 4; j++) {
            int col = bc * kBN + wc * 32 + j * 8 + lr * 2;
#pragma unroll
            for (int half = 0; half < 2; half++) {
                int row = r0 + half * 8;
                float v0 = acc[i][j][half * 2 + 0];
                float v1 = acc[i][j][half * 2 + 1];
                if (epi == 0) {
                    *(__half2*)(dsel + (size_t)row * kD + (col - colshift)) =
                        __floats2half2_rn(v0, v1);
                } else if (epi == 1) {
                    v0 = gelu_f(v0 + bias[col]);
                    v1 = gelu_f(v1 + bias[col + 1]);
                    *(__half2*)(Ch + (size_t)row * N + col) = __floats2half2_rn(v0, v1);
                } else {
                    const float* rp = resid + (size_t)row * N + col;
                    float2 rr = *(const float2*)rp;
                    v0 += rr.x; v1 += rr.y;
                    if (bias) { v0 += bias[col]; v1 += bias[col + 1]; }
                    *(float2*)(Cf + (size_t)row * N + col) = make_float2(v0, v1);
                }
            }
        }
    }
}

// ---------------- ksum (fp16 in, fp32 out) ----------------
__global__ __launch_bounds__(512) void ksum_kernel(const __half* __restrict__ k,
                                                   float* __restrict__ ksum) {
    int bn = blockIdx.x;
    int tid = threadIdx.x;
    const __half* base = k + (size_t)bn * kBLK * kD + tid;
    float s = 0.f;
#pragma unroll 8
    for (int c = 0; c < kBLK; c++) s += __half2float(base[(size_t)c * kD]);
    ksum[bn * kD + tid] = s;
}

// ---------------- sinkhorn ----------------
__global__ __launch_bounds__(256) void sinkhorn_kernel(const float* __restrict__ ksum,
                                                       const float* __restrict__ sw,
                                                       const int* __restrict__ tokens,
                                                       float* __restrict__ perm_out,
                                                       float* __restrict__ smask_out) {
    int b = blockIdx.x / kH, h = blockIdx.x % kH;
    int tid = threadIdx.x;
    int n = tid >> 4, m = tid & 15;
    const float* kp = ksum + ((size_t)(b * kNB + n)) * kD + h * kDH;
    const float* wp = sw + (size_t)h * kDH * kNB + m;
    float la = 0.f;
#pragma unroll
    for (int d = 0; d < kDH; d++) la += kp[d] * wp[d * kNB];

    __shared__ float sm[16][17];
    for (int it = 0; it < 8; it++) {
        float mx = la;
#pragma unroll
        for (int o = 8; o >= 1; o >>= 1)
            mx = fmaxf(mx, __shfl_xor_sync(0xffffffffu, mx, o, 16));
        float e = expf(la - mx);
        float sum = e;
#pragma unroll
        for (int o = 8; o >= 1; o >>= 1)
            sum += __shfl_xor_sync(0xffffffffu, sum, o, 16);
        la = la - (mx + logf(sum));
        sm[n][m] = la;
        __syncthreads();
        float cmx = -1e30f;
#pragma unroll
        for (int i = 0; i < 16; i++) cmx = fmaxf(cmx, sm[i][m]);
        float cs = 0.f;
#pragma unroll
        for (int i = 0; i < 16; i++) cs += expf(sm[i][m] - cmx);
        la = la - (cmx + logf(cs));
        __syncthreads();
    }
    float p = expf(la);
    sm[n][m] = p;
    perm_out[((size_t)(b * kH + h) * kNB + n) * kNB + m] = p;
    __syncthreads();
    for (int idx = tid; idx < kNB * kBLK; idx += 256) {
        int nn = idx >> 7, c = idx & 127;
        float s = 0.f;
#pragma unroll
        for (int mm = 0; mm < 16; mm++) {
            float mb = (tokens[b * kS + mm * kBLK + c] > 0) ? 1.f : 0.f;
            s += sm[nn][mm] * mb;
        }
        smask_out[((size_t)(b * kH + h) * kNB + nn) * kBLK + c] = (s > 0.5f) ? 1.f : 0.f;
    }
}

// ---------------- sort-mix (fp16 in/out, fp32 accumulate) ----------------
__global__ __launch_bounds__(256) void sortmix_kernel(const float* __restrict__ perm,
                                                      const __half* __restrict__ k,
                                                      const __half* __restrict__ v,
                                                      __half* __restrict__ sk,
                                                      __half* __restrict__ sv) {
    int chunk = blockIdx.x;
    int h = blockIdx.y;
    int b = blockIdx.z;
    __shared__ float P[16][16];
    __shared__ float T[16][512];
    int tid = threadIdx.x;
    P[tid >> 4][tid & 15] = perm[(size_t)(b * kH + h) * 256 + tid];
    int cd0 = chunk * 512;

    for (int phase = 0; phase < 2; phase++) {
        const __half* src = phase ? v : k;
        __half* dst = phase ? sv : sk;
        __syncthreads();
        for (int idx = tid; idx < 16 * 512; idx += 256) {
            int m = idx >> 9;
            int j = idx & 511;
            int cd = cd0 + j;
            int c = cd >> 6, d = cd & 63;
            T[m][j] = __half2float(src[((size_t)(b * kS + m * kBLK + c)) * kD + h * kDH + d]);
        }
        __syncthreads();
        for (int idx = tid; idx < 16 * 512; idx += 256) {
            int n = idx >> 9;
            int j = idx & 511;
            float acc = 0.f;
#pragma unroll
            for (int m = 0; m < 16; m++) acc += P[n][m] * T[m][j];
            int cd = cd0 + j;
            int c = cd >> 6, d = cd & 63;
            dst[((size_t)(b * kS + n * kBLK + c)) * kD + h * kDH + d] = __float2half_rn(acc);
        }
    }
}

// ---------------- attention: mma.sync flash-style ----------------
constexpr int kAPitch = 72;
constexpr int kAttnQ = 128 * kAPitch;
constexpr int kAttnKV = 256 * kAPitch;
constexpr int kAttnSmem = (kAttnQ + 2 * kAttnKV) * 2 + 256 * 4 + 16;

__global__ __launch_bounds__(256, 1) void attn_kernel(
    const __half* __restrict__ q, const __half* __restrict__ k,
    const __half* __restrict__ v, const __half* __restrict__ sk,
    const __half* __restrict__ sv, const float* __restrict__ smask,
    const int* __restrict__ tokens, __half* __restrict__ o) {
    extern __shared__ char asm_raw[];
    __half* QS = (__half*)asm_raw;
    __half* KS = QS + kAttnQ;
    __half* VS = KS + kAttnKV;
    float* biasS = (float*)(VS + kAttnKV);

    int n0 = blockIdx.x, h = blockIdx.y, b = blockIdx.z;
    int tid = threadIdx.x, lane = tid & 31, wid = tid >> 5;

    uint32_t qb = smem_u32(QS), kb = smem_u32(KS), vb = smem_u32(VS);
    for (int id = tid; id < 1024; id += 256) {
        int row = id >> 3, ch = id & 7;
        cp16(qb + (uint32_t)row * 144 + ch * 16,
             q + ((size_t)(b * kS + n0 * 128 + row)) * kD + h * 64 + ch * 8);
    }
    for (int id = tid; id < 2048; id += 256) {
        int row = id >> 3, ch = id & 7;
        const __half* src = (row < 128)
            ? k + ((size_t)(b * kS + n0 * 128 + row)) * kD + h * 64 + ch * 8
            : sk + ((size_t)(b * kS + n0 * 128 + row - 128)) * kD + h * 64 + ch * 8;
        cp16(kb + (uint32_t)row * 144 + ch * 16, src);
    }
    for (int id = tid; id < 2048; id += 256) {
        int row = id >> 3, ch = id & 7;
        const __half* src = (row < 128)
            ? v + ((size_t)(b * kS + n0 * 128 + row)) * kD + h * 64 + ch * 8
            : sv + ((size_t)(b * kS + n0 * 128 + row - 128)) * kD + h * 64 + ch * 8;
        cp16(vb + (uint32_t)row * 144 + ch * 16, src);
    }
    asm volatile("cp.async.commit_group;");
    for (int j = tid; j < 256; j += 256) {
        float mv;
        if (j < 128) mv = (tokens[b * kS + n0 * kBLK + j] > 0) ? 1.f : 0.f;
        else mv = smask[((size_t)(b * kH + h) * kNB + n0) * kBLK + (j - 128)];
        biasS[j] = (mv > 0.5f) ? 0.f : -1e9f;
    }
    asm volatile("cp.async.wait_group 0;");
    __syncthreads();

    int r0w = wid * 16;
    int rowoff = (lane & 7) + ((lane >> 3) & 1) * 8;
    int seloff = (lane >> 4) * 8;
    int browoff = (lane & 7) + ((lane >> 4) & 1) * 8;
    int bseloff = ((lane >> 3) & 1) * 8;

    uint32_t aq[4][4];
#pragma unroll
    for (int ks = 0; ks < 4; ks++) {
        uint32_t addr = smem_u32(QS + (r0w + rowoff) * kAPitch + ks * 16 + seloff);
        ldsm_x4(aq[ks][0], aq[ks][1], aq[ks][2], aq[ks][3], addr);
    }

    float sacc[16][8];
#pragma unroll
    for (int nt = 0; nt < 16; nt++)
#pragma unroll
        for (int c = 0; c < 8; c++) sacc[nt][c] = 0.f;

#pragma unroll
    for (int nt = 0; nt < 16; nt++) {
#pragma unroll
        for (int ks = 0; ks < 4; ks++) {
            uint32_t r0, r1, r2, r3;
            uint32_t addr = smem_u32(KS + (nt * 16 + browoff) * kAPitch + ks * 16 + bseloff);
            ldsm_x4(r0, r1, r2, r3, addr);
            mma_f16(&sacc[nt][0], aq[ks][0], aq[ks][1], aq[ks][2], aq[ks][3], r0, r1);
            mma_f16(&sacc[nt][4], aq[ks][0], aq[ks][1], aq[ks][2], aq[ks][3], r2, r3);
        }
    }

    int colbase = (lane & 3) * 2;
    float m0 = -1e30f, m1 = -1e30f;
#pragma unroll
    for (int nt = 0; nt < 16; nt++) {
#pragma unroll
        for (int sub = 0; sub < 2; sub++) {
            float2 bb = *(float2*)&biasS[nt * 16 + sub * 8 + colbase];
            sacc[nt][sub * 4 + 0] += bb.x;
            sacc[nt][sub * 4 + 1] += bb.y;
            sacc[nt][sub * 4 + 2] += bb.x;
            sacc[nt][sub * 4 + 3] += bb.y;
            m0 = fmaxf(m0, fmaxf(sacc[nt][sub * 4 + 0], sacc[nt][sub * 4 + 1]));
            m1 = fmaxf(m1, fmaxf(sacc[nt][sub * 4 + 2], sacc[nt][sub * 4 + 3]));
        }
    }
    m0 = fmaxf(m0, __shfl_xor_sync(0xffffffffu, m0, 1));
    m0 = fmaxf(m0, __shfl_xor_sync(0xffffffffu, m0, 2));
    m1 = fmaxf(m1, __shfl_xor_sync(0xffffffffu, m1, 1));
    m1 = fmaxf(m1, __shfl_xor_sync(0xffffffffu, m1, 2));
    float l0 = 0.f, l1 = 0.f;
#pragma unroll
    for (int nt = 0; nt < 16; nt++) {
#pragma unroll
        for (int sub = 0; sub < 2; sub++) {
            float p0 = __expf(sacc[nt][sub * 4 + 0] - m0);
            float p1 = __expf(sacc[nt][sub * 4 + 1] - m0);
            float p2 = __expf(sacc[nt][sub * 4 + 2] - m1);
            float p3 = __expf(sacc[nt][sub * 4 + 3] - m1);
            sacc[nt][sub * 4 + 0] = p0; sacc[nt][sub * 4 + 1] = p1;
            sacc[nt][sub * 4 + 2] = p2; sacc[nt][sub * 4 + 3] = p3;
            l0 += p0 + p1; l1 += p2 + p3;
        }
    }
    l0 += __shfl_xor_sync(0xffffffffu, l0, 1);
    l0 += __shfl_xor_sync(0xffffffffu, l0, 2);
    l1 += __shfl_xor_sync(0xffffffffu, l1, 1);
    l1 += __shfl_xor_sync(0xffffffffu, l1, 2);

    float oacc[8][4];
#pragma unroll
    for (int i = 0; i < 8; i++)
#pragma unroll
        for (int c = 0; c < 4; c++) oacc[i][c] = 0.f;

#pragma unroll
    for (int kt = 0; kt < 16; kt++) {
        uint32_t pa0 = pack_h2(sacc[kt][0], sacc[kt][1]);
        uint32_t pa1 = pack_h2(sacc[kt][2], sacc[kt][3]);
        uint32_t pa2 = pack_h2(sacc[kt][4], sacc[kt][5]);
        uint32_t pa3 = pack_h2(sacc[kt][6], sacc[kt][7]);
#pragma unroll
        for (int dg = 0; dg < 4; dg++) {
            uint32_t r0, r1, r2, r3;
            uint32_t addr = smem_u32(VS + (kt * 16 + rowoff) * kAPitch + dg * 16 + seloff);
            ldsm_x4t(r0, r1, r2, r3, addr);
            mma_f16(oacc[dg * 2], pa0, pa1, pa2, pa3, r0, r1);
            mma_f16(oacc[dg * 2 + 1], pa0, pa1, pa2, pa3, r2, r3);
        }
    }

    float inv0 = 1.f / l0, inv1 = 1.f / l1;
    int row0 = n0 * 128 + r0w + (lane >> 2);
#pragma unroll
    for (int dsub = 0; dsub < 8; dsub++) {
        int col = h * 64 + dsub * 8 + colbase;
        *(__half2*)(o + ((size_t)(b * kS + row0)) * kD + col) =
            __floats2half2_rn(oacc[dsub][0] * inv0, oacc[dsub][1] * inv0);
        *(__half2*)(o + ((size_t)(b * kS + row0 + 8)) * kD + col) =
            __floats2half2_rn(oacc[dsub][2] * inv1, oacc[dsub][3] * inv1);
    }
}

// ---------------- host orchestration ----------------
extern "C" void kernel_launch(void* const* d_in, const int* in_sizes, int n_in,
                              void* d_out, int out_size) {
    const int* tokens = (const int*)d_in[0];
    const float* embed = (const float*)d_in[1];
    const float* ln1_s = (const float*)d_in[2];
    const float* ln1_b = (const float*)d_in[3];
    const float* wq = (const float*)d_in[4];
    const float* wk = (const float*)d_in[5];
    const float* wv = (const float*)d_in[6];
    const float* wo = (const float*)d_in[7];
    const float* sortw = (const float*)d_in[8];
    const float* ln2_s = (const float*)d_in[9];
    const float* ln2_b = (const float*)d_in[10];
    const float* w1 = (const float*)d_in[11];
    const float* b1 = (const float*)d_in[12];
    const float* w2 = (const float*)d_in[13];
    const float* b2 = (const float*)d_in[14];
    const float* lnf_s = (const float*)d_in[15];
    const float* lnf_b = (const float*)d_in[16];
    float* out = (float*)d_out;

    float *x, *ksum, *perm, *smask;
    __half *qh, *kh, *vh, *skh, *svh, *hh, *oh, *mlph, *wqkv, *woh, *w1h, *w2h;
    cudaGetSymbolAddress((void**)&x, g_x);
    cudaGetSymbolAddress((void**)&qh, g_qh);
    cudaGetSymbolAddress((void**)&kh, g_kh);
    cudaGetSymbolAddress((void**)&vh, g_vh);
    cudaGetSymbolAddress((void**)&skh, g_skh);
    cudaGetSymbolAddress((void**)&svh, g_svh);
    cudaGetSymbolAddress((void**)&ksum, g_ksum);
    cudaGetSymbolAddress((void**)&perm, g_perm);
    cudaGetSymbolAddress((void**)&smask, g_smask);
    cudaGetSymbolAddress((void**)&hh, g_hh);
    cudaGetSymbolAddress((void**)&oh, g_oh);
    cudaGetSymbolAddress((void**)&mlph, g_mlph);
    cudaGetSymbolAddress((void**)&wqkv, g_wqkv);
    cudaGetSymbolAddress((void**)&woh, g_wo_h);
    cudaGetSymbolAddress((void**)&w1h, g_w1_h);
    cudaGetSymbolAddress((void**)&w2h, g_w2_h);

    cudaFuncSetAttribute(hgemm_kernel, cudaFuncAttributeMaxDynamicSharedMemorySize,
                         kSmemBytes);
    cudaFuncSetAttribute(attn_kernel, cudaFuncAttributeMaxDynamicSharedMemorySize,
                         kAttnSmem);

    int nW = kL * kD * kD;
    int nM = kL * kD * kMLP;
    {
        dim3 g(nM / 4 / 256, 6);
        wconv_kernel<<<g, 256>>>(wq, wk, wv, wo, w1, w2,
                                 wqkv, woh, w1h, w2h, nW, nM);
    }

    embed_pe_kernel<<<(kBSD + 255) / 256, 256>>>(tokens, embed, x);

    dim3 gQKV(kQKV / 128, kBS / 128);   // (12, 64)
    dim3 gD(kD / 128, kBS / 128);       // (4, 64)
    dim3 gM(kMLP / 128, kBS / 128);     // (16, 64)

    for (int l = 0; l < kL; l++) {
        __half* wqkv_l = wqkv + (size_t)l * kD * kQKV;
        __half* wo_l = woh + (size_t)l * kD * kD;
        const float* sw_l = sortw + (size_t)l * kH * kDH * kNB;
        __half* w1_l = w1h + (size_t)l * kD * kMLP;
        const float* b1_l = b1 + (size_t)l * kMLP;
        __half* w2_l = w2h + (size_t)l * kMLP * kD;
        const float* b2_l = b2 + (size_t)l * kD;

        ln_kernel<<<kBS, 128>>>(x, ln1_s + l * kD, ln1_b + l * kD, hh, nullptr);
        hgemm_kernel<<<gQKV, 256, kSmemBytes>>>(kBS, kQKV, kD, hh, wqkv_l,
                                                nullptr, nullptr, nullptr, qh, kh, vh, 0);

        ksum_kernel<<<kB * kNB, 512>>>(kh, ksum);
        sinkhorn_kernel<<<kB * kH, 256>>>(ksum, sw_l, tokens, perm, smask);
        sortmix_kernel<<<dim3(16, kH, kB), 256>>>(perm, kh, vh, skh, svh);

        attn_kernel<<<dim3(kNB, kH, kB), 256, kAttnSmem>>>(qh, kh, vh, skh, svh,
                                                           smask, tokens, oh);

        // x = x + o @ wo
        hgemm_kernel<<<gD, 256, kSmemBytes>>>(kBS, kD, kD, oh, wo_l,
                                              nullptr, x, x, nullptr, nullptr, nullptr, 2);

        // MLP
        ln_kernel<<<kBS, 128>>>(x, ln2_s + l * kD, ln2_b + l * kD, hh, nullptr);
        hgemm_kernel<<<gM, 256, kSmemBytes>>>(kBS, kMLP, kD, hh, w1_l,
                                              b1_l, nullptr, nullptr, mlph, nullptr, nullptr, 1);
        hgemm_kernel<<<gD, 256, kSmemBytes>>>(kBS, kD, kMLP, mlph, w2_l,
                                              b2_l, x, x, nullptr, nullptr, nullptr, 2);
    }

    ln_kernel<<<kBS, 128>>>(x, lnf_s, lnf_b, nullptr, out);
}

// round 12
// speedup vs baseline: 1.0702x; 1.0114x over previous
#include <cuda_runtime.h>
#include <cuda_fp16.h>
#include <math.h>
#include <stdint.h>

// ---------------- problem dims ----------------
constexpr int kB = 4, kS = 2048, kD = 512, kH = 8, kDH = 64;
constexpr int kMLP = 2048, kBLK = 128, kNB = 16, kL = 4;
constexpr int kBS = kB * kS;                 // 8192 rows
constexpr int kBSD = kBS * kD;               // 4,194,304
constexpr int kQKV = 3 * kD;                 // 1536

// ---------------- scratch (static device globals; no allocation) ----------------
static __device__ float g_x[kBSD];
static __device__ __align__(256) __half g_qh[kBSD];
static __device__ __align__(256) __half g_kh[kBSD];
static __device__ __align__(256) __half g_vh[kBSD];
static __device__ __align__(256) __half g_skh[kBSD];
static __device__ __align__(256) __half g_svh[kBSD];
static __device__ __align__(256) __half g_hh[kBSD];          // LN outputs (fp16)
static __device__ __align__(256) __half g_oh[kBSD];          // attention out (fp16)
static __device__ __align__(256) __half g_mlph[kBS * kMLP];  // gelu out (fp16)
static __device__ __align__(256) __half g_wqkv[kL * kD * kQKV]; // [l][k][qkv-col]
static __device__ __align__(256) __half g_wo_h[kL * kD * kD];
static __device__ __align__(256) __half g_w1_h[kL * kD * kMLP];
static __device__ __align__(256) __half g_w2_h[kL * kMLP * kD];
static __device__ float g_ksum[kB * kNB * kD];
static __device__ float g_perm[kB * kH * kNB * kNB];
static __device__ float g_smask[kB * kH * kNB * kBLK];

// ---------------- fp32 -> fp16 weight conversion (6 segments, 1 launch) ----------------
// seg 0/1/2: wq(x1/8)/wk/wv -> wqkv concat; seg 3: wo; seg 4: w1; seg 5: w2
__global__ void wconv_kernel(const float* __restrict__ s0, const float* __restrict__ s1,
                             const float* __restrict__ s2, const float* __restrict__ s3,
                             const float* __restrict__ s4, const float* __restrict__ s5,
                             __half* __restrict__ dqkv, __half* __restrict__ d3,
                             __half* __restrict__ d4, __half* __restrict__ d5,
                             int nW, int nM) {
    int seg = blockIdx.y;
    int n = (seg < 4) ? nW : nM;
    int i = (blockIdx.x * 256 + threadIdx.x) * 4;
    if (i >= n) return;
    const float* s;
    float scale = 1.0f;
    switch (seg) {
        case 0: s = s0; scale = 0.125f; break;
        case 1: s = s1; break;
        case 2: s = s2; break;
        case 3: s = s3; break;
        case 4: s = s4; break;
        default: s = s5; break;
    }
    float4 f = *(const float4*)(s + i);
    f.x *= scale; f.y *= scale; f.z *= scale; f.w *= scale;
    __half2 h0 = __floats2half2_rn(f.x, f.y);
    __half2 h1 = __floats2half2_rn(f.z, f.w);
    if (seg < 3) {
        int l = i >> 18;                 // / (512*512)
        int rem = i & ((1 << 18) - 1);
        int row = rem >> 9, col = rem & 511;
        __half2* dp = (__half2*)(dqkv + (size_t)l * kD * kQKV + (size_t)row * kQKV +
                                 seg * kD + col);
        dp[0] = h0; dp[1] = h1;
    } else {
        __half* d = (seg == 3) ? d3 : (seg == 4) ? d4 : d5;
        __half2* dp = (__half2*)(d + i);
        dp[0] = h0; dp[1] = h1;
    }
}

// ---------------- embed + positional encoding ----------------
__global__ void embed_pe_kernel(const int* __restrict__ tokens,
                                const float* __restrict__ embed,
                                float* __restrict__ x) {
    int idx = blockIdx.x * 256 + threadIdx.x;
    if (idx >= kBSD) return;
    int d = idx & (kD - 1);
    int bs = idx >> 9;
    int s = bs & (kS - 1);
    int tok = tokens[bs];
    int i2 = (d >> 1) * 2;
    float freq = expf(-(float)i2 * (logf(10000.0f) / (float)kD));
    float ang = (float)s * freq;
    float pe = (d & 1) ? cosf(ang) : sinf(ang);
    x[idx] = embed[tok * kD + d] + pe;
}

// ---------------- layernorm: fp32 in, fp16 out (or fp32 for final) ----------------
__global__ __launch_bounds__(128) void ln_kernel(const float* __restrict__ x,
                                                 const float* __restrict__ sc,
                                                 const float* __restrict__ bi,
                                                 __half* __restrict__ outh,
                                                 float* __restrict__ outf) {
    int row = blockIdx.x;
    const float* xp = x + (size_t)row * kD;
    float v[4];
    float s = 0.f, ss = 0.f;
#pragma unroll
    for (int i = 0; i < 4; i++) {
        v[i] = xp[threadIdx.x + i * 128];
        s += v[i];
        ss += v[i] * v[i];
    }
#pragma unroll
    for (int o = 16; o >= 1; o >>= 1) {
        s += __shfl_down_sync(0xffffffffu, s, o);
        ss += __shfl_down_sync(0xffffffffu, ss, o);
    }
    __shared__ float sa[4], sb[4];
    int w = threadIdx.x >> 5;
    if ((threadIdx.x & 31) == 0) { sa[w] = s; sb[w] = ss; }
    __syncthreads();
    s = sa[0] + sa[1] + sa[2] + sa[3];
    ss = sb[0] + sb[1] + sb[2] + sb[3];
    float mean = s * (1.0f / kD);
    float var = ss * (1.0f / kD) - mean * mean;
    float r = rsqrtf(var + 1e-6f);
#pragma unroll
    for (int i = 0; i < 4; i++) {
        int d = threadIdx.x + i * 128;
        float o = (v[i] - mean) * r * sc[d] + bi[d];
        if (outh) outh[(size_t)row * kD + d] = __float2half_rn(o);
        else outf[(size_t)row * kD + d] = o;
    }
}

// ---------------- mma helpers ----------------
__device__ __forceinline__ float gelu_f(float x) {
    const float c = 0.7978845608028654f;
    float x3 = x * x * x;
    return 0.5f * x * (1.0f + tanhf(c * (x + 0.044715f * x3)));
}
__device__ __forceinline__ uint32_t smem_u32(const void* p) {
    return (uint32_t)__cvta_generic_to_shared(p);
}
__device__ __forceinline__ void ldsm_x4(uint32_t& r0, uint32_t& r1, uint32_t& r2,
                                        uint32_t& r3, uint32_t addr) {
    asm volatile("ldmatrix.sync.aligned.m8n8.x4.shared.b16 {%0,%1,%2,%3},[%4];"
                 : "=r"(r0), "=r"(r1), "=r"(r2), "=r"(r3) : "r"(addr));
}
__device__ __forceinline__ void ldsm_x4t(uint32_t& r0, uint32_t& r1, uint32_t& r2,
                                         uint32_t& r3, uint32_t addr) {
    asm volatile("ldmatrix.sync.aligned.m8n8.x4.trans.shared.b16 {%0,%1,%2,%3},[%4];"
                 : "=r"(r0), "=r"(r1), "=r"(r2), "=r"(r3) : "r"(addr));
}
__device__ __forceinline__ void mma_f16(float* c, uint32_t a0, uint32_t a1,
                                        uint32_t a2, uint32_t a3,
                                        uint32_t b0, uint32_t b1) {
    asm volatile(
        "mma.sync.aligned.m16n8k16.row.col.f32.f16.f16.f32 "
        "{%0,%1,%2,%3},{%4,%5,%6,%7},{%8,%9},{%0,%1,%2,%3};"
        : "+f"(c[0]), "+f"(c[1]), "+f"(c[2]), "+f"(c[3])
        : "r"(a0), "r"(a1), "r"(a2), "r"(a3), "r"(b0), "r"(b1));
}
__device__ __forceinline__ void cp16(uint32_t dst, const void* src) {
    asm volatile("cp.async.cg.shared.global [%0],[%1],16;" :: "r"(dst), "l"(src));
}
__device__ __forceinline__ uint32_t pack_h2(float a, float b) {
    __half2 h = __floats2half2_rn(a, b);
    return *(uint32_t*)&h;
}

// ---------------- fp16 tensor-core GEMM (3-stage, BK=64, 8 warps, 64x32 tiles) ----------------
constexpr int kStages = 3;
constexpr int kBM = 128, kBN = 128, kBKg = 64;
constexpr int kAP = 72, kBP = 136;
constexpr int kASTG = kBM * kAP;                  // 9216 halves
constexpr int kBSTG = kBKg * kBP;                 // 8704 halves
constexpr int kSmemHalves = kStages * (kASTG + kBSTG);
constexpr int kSmemBytes = kSmemHalves * 2;       // 107520

// epi 0: QKV triple-output fp16 (Nout=512 each; segment by bc>>2)
// epi 1: Ch = gelu(acc + bias) (fp16)
// epi 2: Cf = resid + acc + (bias? bias : 0) (fp32)
__global__ __launch_bounds__(256, 2) void hgemm_kernel(
    int M, int N, int K,
    const __half* __restrict__ A, const __half* __restrict__ Bm,
    const float* __restrict__ bias, const float* __restrict__ resid,
    float* __restrict__ Cf, __half* __restrict__ Ch,
    __half* __restrict__ Chk, __half* __restrict__ Chv, int epi) {
    extern __shared__ __half smem[];
    __half* As = smem;
    __half* Bs = smem + kStages * kASTG;

    int tid = threadIdx.x, lane = tid & 31, w = tid >> 5;
    int wr = w >> 2, wc = w & 3;       // 2x4 warp grid, warp tile 64x32
    int br = blockIdx.y, bc = blockIdx.x;
    const __half* Ap = A + (size_t)br * kBM * K;
    const __half* Bp = Bm + (size_t)bc * kBN;

    float acc[4][4][4];
#pragma unroll
    for (int i = 0; i < 4; i++)
#pragma unroll
        for (int j = 0; j < 4; j++)
#pragma unroll
            for (int r = 0; r < 4; r++) acc[i][j][r] = 0.f;

    auto issue = [&](int stage, int k0) {
        uint32_t ab = smem_u32(As + stage * kASTG);
        uint32_t bb = smem_u32(Bs + stage * kBSTG);
#pragma unroll
        for (int p = 0; p < 4; p++) {
            int id = tid + p * 256;
            int ar = id >> 3, ac = id & 7;          // A: 128 rows x 8 chunks
            cp16(ab + (uint32_t)(ar * kAP + ac * 8) * 2, Ap + (size_t)ar * K + k0 + ac * 8);
            int brr = id >> 4, bcc = id & 15;       // B: 64 rows x 16 chunks
            cp16(bb + (uint32_t)(brr * kBP + bcc * 8) * 2,
                 Bp + (size_t)(k0 + brr) * N + bcc * 8);
        }
        asm volatile("cp.async.commit_group;");
    };

    int nt = K / kBKg;
#pragma unroll
    for (int t = 0; t < kStages - 1; t++) issue(t, t * kBKg);

    int rowoff = (lane & 7) + ((lane >> 3) & 1) * 8;
    int seloff = (lane >> 4) * 8;

    for (int t = 0; t < nt; t++) {
        asm volatile("cp.async.wait_group %0;" :: "n"(kStages - 2));
        __syncthreads();
        int tn = t + kStages - 1;
        if (tn < nt) issue(tn % kStages, tn * kBKg);
        int buf = t % kStages;
        const __half* Ab = As + buf * kASTG;
        const __half* Bb = Bs + buf * kBSTG;

        // 4 k-slices of 16; 2-slot rolling fragment prefetch
        uint32_t af[2][4][4], bf[2][4][2];
        auto load_frags = [&](int slot, int s) {
            int k0 = s * 16;
#pragma unroll
            for (int i = 0; i < 4; i++) {
                int m0 = wr * 64 + i * 16;
                uint32_t addr = smem_u32(Ab + (m0 + rowoff) * kAP + k0 + seloff);
                ldsm_x4(af[slot][i][0], af[slot][i][1], af[slot][i][2], af[slot][i][3], addr);
            }
#pragma unroll
            for (int j2 = 0; j2 < 2; j2++) {
                int n0 = wc * 32 + j2 * 16;
                uint32_t addr = smem_u32(Bb + (k0 + rowoff) * kBP + n0 + seloff);
                uint32_t r0, r1, r2, r3;
                ldsm_x4t(r0, r1, r2, r3, addr);
                bf[slot][j2 * 2][0] = r0; bf[slot][j2 * 2][1] = r1;
                bf[slot][j2 * 2 + 1][0] = r2; bf[slot][j2 * 2 + 1][1] = r3;
            }
        };
        load_frags(0, 0);
#pragma unroll
        for (int s = 0; s < 4; s++) {
            int cur = s & 1;
            if (s + 1 < 4) load_frags(cur ^ 1, s + 1);
#pragma unroll
            for (int i = 0; i < 4; i++)
#pragma unroll
                for (int j = 0; j < 4; j++)
                    mma_f16(acc[i][j], af[cur][i][0], af[cur][i][1], af[cur][i][2],
                            af[cur][i][3], bf[cur][j][0], bf[cur][j][1]);
        }
    }

    int lq = lane >> 2, lr = lane & 3;
    // QKV segment dispatch (epi 0 only)
    __half* dsel = Ch;
    int colshift = 0;
    if (epi == 0) {
        int seg = bc >> 2;                 // 128-col blocks: 0-3 q, 4-7 k, 8-11 v
        dsel = (seg == 0) ? Ch : (seg == 1) ? Chk : Chv;
        colshift = seg * 512;
    }
#pragma unroll
    for (int i = 0; i < 4; i++) {
        int r0 = br * kBM + wr * 64 + i * 16 + lq;
#pragma unroll
        for (int j = 0; j < 4; j++) {
            int col = bc * kBN + wc * 32 + j * 8 + lr * 2;
#pragma unroll
            for (int half = 0; half < 2; half++) {
                int row = r0 + half * 8;
                float v0 = acc[i][j][half * 2 + 0];
                float v1 = acc[i][j][half * 2 + 1];
                if (epi == 0) {
                    *(__half2*)(dsel + (size_t)row * kD + (col - colshift)) =
                        __floats2half2_rn(v0, v1);
                } else if (epi == 1) {
                    v0 = gelu_f(v0 + bias[col]);
                    v1 = gelu_f(v1 + bias[col + 1]);
                    *(__half2*)(Ch + (size_t)row * N + col) = __floats2half2_rn(v0, v1);
                } else {
                    const float* rp = resid + (size_t)row * N + col;
                    float2 rr = *(const float2*)rp;
                    v0 += rr.x; v1 += rr.y;
                    if (bias) { v0 += bias[col]; v1 += bias[col + 1]; }
                    *(float2*)(Cf + (size_t)row * N + col) = make_float2(v0, v1);
                }
            }
        }
    }
}

// ---------------- ksum (fp16 in, fp32 out) ----------------
__global__ __launch_bounds__(512) void ksum_kernel(const __half* __restrict__ k,
                                                   float* __restrict__ ksum) {
    int bn = blockIdx.x;
    int tid = threadIdx.x;
    const __half* base = k + (size_t)bn * kBLK * kD + tid;
    float s = 0.f;
#pragma unroll 8
    for (int c = 0; c < kBLK; c++) s += __half2float(base[(size_t)c * kD]);
    ksum[bn * kD + tid] = s;
}

// ---------------- sinkhorn ----------------
__global__ __launch_bounds__(256) void sinkhorn_kernel(const float* __restrict__ ksum,
                                                       const float* __restrict__ sw,
                                                       const int* __restrict__ tokens,
                                                       float* __restrict__ perm_out,
                                                       float* __restrict__ smask_out) {
    int b = blockIdx.x / kH, h = blockIdx.x % kH;
    int tid = threadIdx.x;
    int n = tid >> 4, m = tid & 15;
    const float* kp = ksum + ((size_t)(b * kNB + n)) * kD + h * kDH;
    const float* wp = sw + (size_t)h * kDH * kNB + m;
    float la = 0.f;
#pragma unroll
    for (int d = 0; d < kDH; d++) la += kp[d] * wp[d * kNB];

    __shared__ float sm[16][17];
    for (int it = 0; it < 8; it++) {
        float mx = la;
#pragma unroll
        for (int o = 8; o >= 1; o >>= 1)
            mx = fmaxf(mx, __shfl_xor_sync(0xffffffffu, mx, o, 16));
        float e = expf(la - mx);
        float sum = e;
#pragma unroll
        for (int o = 8; o >= 1; o >>= 1)
            sum += __shfl_xor_sync(0xffffffffu, sum, o, 16);
        la = la - (mx + logf(sum));
        sm[n][m] = la;
        __syncthreads();
        float cmx = -1e30f;
#pragma unroll
        for (int i = 0; i < 16; i++) cmx = fmaxf(cmx, sm[i][m]);
        float cs = 0.f;
#pragma unroll
        for (int i = 0; i < 16; i++) cs += expf(sm[i][m] - cmx);
        la = la - (cmx + logf(cs));
        __syncthreads();
    }
    float p = expf(la);
    sm[n][m] = p;
    perm_out[((size_t)(b * kH + h) * kNB + n) * kNB + m] = p;
    __syncthreads();
    for (int idx = tid; idx < kNB * kBLK; idx += 256) {
        int nn = idx >> 7, c = idx & 127;
        float s = 0.f;
#pragma unroll
        for (int mm = 0; mm < 16; mm++) {
            float mb = (tokens[b * kS + mm * kBLK + c] > 0) ? 1.f : 0.f;
            s += sm[nn][mm] * mb;
        }
        smask_out[((size_t)(b * kH + h) * kNB + nn) * kBLK + c] = (s > 0.5f) ? 1.f : 0.f;
    }
}

// ---------------- sort-mix (fp16 in/out, fp32 accumulate) ----------------
__global__ __launch_bounds__(256) void sortmix_kernel(const float* __restrict__ perm,
                                                      const __half* __restrict__ k,
                                                      const __half* __restrict__ v,
                                                      __half* __restrict__ sk,
                                                      __half* __restrict__ sv) {
    int chunk = blockIdx.x;
    int h = blockIdx.y;
    int b = blockIdx.z;
    __shared__ float P[16][16];
    __shared__ float T[16][512];
    int tid = threadIdx.x;
    P[tid >> 4][tid & 15] = perm[(size_t)(b * kH + h) * 256 + tid];
    int cd0 = chunk * 512;

    for (int phase = 0; phase < 2; phase++) {
        const __half* src = phase ? v : k;
        __half* dst = phase ? sv : sk;
        __syncthreads();
        for (int idx = tid; idx < 16 * 512; idx += 256) {
            int m = idx >> 9;
            int j = idx & 511;
            int cd = cd0 + j;
            int c = cd >> 6, d = cd & 63;
            T[m][j] = __half2float(src[((size_t)(b * kS + m * kBLK + c)) * kD + h * kDH + d]);
        }
        __syncthreads();
        for (int idx = tid; idx < 16 * 512; idx += 256) {
            int n = idx >> 9;
            int j = idx & 511;
            float acc = 0.f;
#pragma unroll
            for (int m = 0; m < 16; m++) acc += P[n][m] * T[m][j];
            int cd = cd0 + j;
            int c = cd >> 6, d = cd & 63;
            dst[((size_t)(b * kS + n * kBLK + c)) * kD + h * kDH + d] = __float2half_rn(acc);
        }
    }
}

// ---------------- attention: mma.sync flash-style ----------------
constexpr int kAPitch = 72;
constexpr int kAttnQ = 128 * kAPitch;
constexpr int kAttnKV = 256 * kAPitch;
constexpr int kAttnSmem = (kAttnQ + 2 * kAttnKV) * 2 + 256 * 4 + 16;

__global__ __launch_bounds__(256, 1) void attn_kernel(
    const __half* __restrict__ q, const __half* __restrict__ k,
    const __half* __restrict__ v, const __half* __restrict__ sk,
    const __half* __restrict__ sv, const float* __restrict__ smask,
    const int* __restrict__ tokens, __half* __restrict__ o) {
    extern __shared__ char asm_raw[];
    __half* QS = (__half*)asm_raw;
    __half* KS = QS + kAttnQ;
    __half* VS = KS + kAttnKV;
    float* biasS = (float*)(VS + kAttnKV);

    int n0 = blockIdx.x, h = blockIdx.y, b = blockIdx.z;
    int tid = threadIdx.x, lane = tid & 31, wid = tid >> 5;

    uint32_t qb = smem_u32(QS), kb = smem_u32(KS), vb = smem_u32(VS);
    for (int id = tid; id < 1024; id += 256) {
        int row = id >> 3, ch = id & 7;
        cp16(qb + (uint32_t)row * 144 + ch * 16,
             q + ((size_t)(b * kS + n0 * 128 + row)) * kD + h * 64 + ch * 8);
    }
    for (int id = tid; id < 2048; id += 256) {
        int row = id >> 3, ch = id & 7;
        const __half* src = (row < 128)
            ? k + ((size_t)(b * kS + n0 * 128 + row)) * kD + h * 64 + ch * 8
            : sk + ((size_t)(b * kS + n0 * 128 + row - 128)) * kD + h * 64 + ch * 8;
        cp16(kb + (uint32_t)row * 144 + ch * 16, src);
    }
    for (int id = tid; id < 2048; id += 256) {
        int row = id >> 3, ch = id & 7;
        const __half* src = (row < 128)
            ? v + ((size_t)(b * kS + n0 * 128 + row)) * kD + h * 64 + ch * 8
            : sv + ((size_t)(b * kS + n0 * 128 + row - 128)) * kD + h * 64 + ch * 8;
        cp16(vb + (uint32_t)row * 144 + ch * 16, src);
    }
    asm volatile("cp.async.commit_group;");
    for (int j = tid; j < 256; j += 256) {
        float mv;
        if (j < 128) mv = (tokens[b * kS + n0 * kBLK + j] > 0) ? 1.f : 0.f;
        else mv = smask[((size_t)(b * kH + h) * kNB + n0) * kBLK + (j - 128)];
        biasS[j] = (mv > 0.5f) ? 0.f : -1e9f;
    }
    asm volatile("cp.async.wait_group 0;");
    __syncthreads();

    int r0w = wid * 16;
    int rowoff = (lane & 7) + ((lane >> 3) & 1) * 8;
    int seloff = (lane >> 4) * 8;
    int browoff = (lane & 7) + ((lane >> 4) & 1) * 8;
    int bseloff = ((lane >> 3) & 1) * 8;

    uint32_t aq[4][4];
#pragma unroll
    for (int ks = 0; ks < 4; ks++) {
        uint32_t addr = smem_u32(QS + (r0w + rowoff) * kAPitch + ks * 16 + seloff);
        ldsm_x4(aq[ks][0], aq[ks][1], aq[ks][2], aq[ks][3], addr);
    }

    float sacc[16][8];
#pragma unroll
    for (int nt = 0; nt < 16; nt++)
#pragma unroll
        for (int c = 0; c < 8; c++) sacc[nt][c] = 0.f;

#pragma unroll
    for (int nt = 0; nt < 16; nt++) {
#pragma unroll
        for (int ks = 0; ks < 4; ks++) {
            uint32_t r0, r1, r2, r3;
            uint32_t addr = smem_u32(KS + (nt * 16 + browoff) * kAPitch + ks * 16 + bseloff);
            ldsm_x4(r0, r1, r2, r3, addr);
            mma_f16(&sacc[nt][0], aq[ks][0], aq[ks][1], aq[ks][2], aq[ks][3], r0, r1);
            mma_f16(&sacc[nt][4], aq[ks][0], aq[ks][1], aq[ks][2], aq[ks][3], r2, r3);
        }
    }

    int colbase = (lane & 3) * 2;
    float m0 = -1e30f, m1 = -1e30f;
#pragma unroll
    for (int nt = 0; nt < 16; nt++) {
#pragma unroll
        for (int sub = 0; sub < 2; sub++) {
            float2 bb = *(float2*)&biasS[nt * 16 + sub * 8 + colbase];
            sacc[nt][sub * 4 + 0] += bb.x;
            sacc[nt][sub * 4 + 1] += bb.y;
            sacc[nt][sub * 4 + 2] += bb.x;
            sacc[nt][sub * 4 + 3] += bb.y;
            m0 = fmaxf(m0, fmaxf(sacc[nt][sub * 4 + 0], sacc[nt][sub * 4 + 1]));
            m1 = fmaxf(m1, fmaxf(sacc[nt][sub * 4 + 2], sacc[nt][sub * 4 + 3]));
        }
    }
    m0 = fmaxf(m0, __shfl_xor_sync(0xffffffffu, m0, 1));
    m0 = fmaxf(m0, __shfl_xor_sync(0xffffffffu, m0, 2));
    m1 = fmaxf(m1, __shfl_xor_sync(0xffffffffu, m1, 1));
    m1 = fmaxf(m1, __shfl_xor_sync(0xffffffffu, m1, 2));
    float l0 = 0.f, l1 = 0.f;
#pragma unroll
    for (int nt = 0; nt < 16; nt++) {
#pragma unroll
        for (int sub = 0; sub < 2; sub++) {
            float p0 = __expf(sacc[nt][sub * 4 + 0] - m0);
            float p1 = __expf(sacc[nt][sub * 4 + 1] - m0);
            float p2 = __expf(sacc[nt][sub * 4 + 2] - m1);
            float p3 = __expf(sacc[nt][sub * 4 + 3] - m1);
            sacc[nt][sub * 4 + 0] = p0; sacc[nt][sub * 4 + 1] = p1;
            sacc[nt][sub * 4 + 2] = p2; sacc[nt][sub * 4 + 3] = p3;
            l0 += p0 + p1; l1 += p2 + p3;
        }
    }
    l0 += __shfl_xor_sync(0xffffffffu, l0, 1);
    l0 += __shfl_xor_sync(0xffffffffu, l0, 2);
    l1 += __shfl_xor_sync(0xffffffffu, l1, 1);
    l1 += __shfl_xor_sync(0xffffffffu, l1, 2);

    float oacc[8][4];
#pragma unroll
    for (int i = 0; i < 8; i++)
#pragma unroll
        for (int c = 0; c < 4; c++) oacc[i][c] = 0.f;

#pragma unroll
    for (int kt = 0; kt < 16; kt++) {
        uint32_t pa0 = pack_h2(sacc[kt][0], sacc[kt][1]);
        uint32_t pa1 = pack_h2(sacc[kt][2], sacc[kt][3]);
        uint32_t pa2 = pack_h2(sacc[kt][4], sacc[kt][5]);
        uint32_t pa3 = pack_h2(sacc[kt][6], sacc[kt][7]);
#pragma unroll
        for (int dg = 0; dg < 4; dg++) {
            uint32_t r0, r1, r2, r3;
            uint32_t addr = smem_u32(VS + (kt * 16 + rowoff) * kAPitch + dg * 16 + seloff);
            ldsm_x4t(r0, r1, r2, r3, addr);
            mma_f16(oacc[dg * 2], pa0, pa1, pa2, pa3, r0, r1);
            mma_f16(oacc[dg * 2 + 1], pa0, pa1, pa2, pa3, r2, r3);
        }
    }

    float inv0 = 1.f / l0, inv1 = 1.f / l1;
    int row0 = n0 * 128 + r0w + (lane >> 2);
#pragma unroll
    for (int dsub = 0; dsub < 8; dsub++) {
        int col = h * 64 + dsub * 8 + colbase;
        *(__half2*)(o + ((size_t)(b * kS + row0)) * kD + col) =
            __floats2half2_rn(oacc[dsub][0] * inv0, oacc[dsub][1] * inv0);
        *(__half2*)(o + ((size_t)(b * kS + row0 + 8)) * kD + col) =
            __floats2half2_rn(oacc[dsub][2] * inv1, oacc[dsub][3] * inv1);
    }
}

// ---------------- host orchestration ----------------
extern "C" void kernel_launch(void* const* d_in, const int* in_sizes, int n_in,
                              void* d_out, int out_size) {
    const int* tokens = (const int*)d_in[0];
    const float* embed = (const float*)d_in[1];
    const float* ln1_s = (const float*)d_in[2];
    const float* ln1_b = (const float*)d_in[3];
    const float* wq = (const float*)d_in[4];
    const float* wk = (const float*)d_in[5];
    const float* wv = (const float*)d_in[6];
    const float* wo = (const float*)d_in[7];
    const float* sortw = (const float*)d_in[8];
    const float* ln2_s = (const float*)d_in[9];
    const float* ln2_b = (const float*)d_in[10];
    const float* w1 = (const float*)d_in[11];
    const float* b1 = (const float*)d_in[12];
    const float* w2 = (const float*)d_in[13];
    const float* b2 = (const float*)d_in[14];
    const float* lnf_s = (const float*)d_in[15];
    const float* lnf_b = (const float*)d_in[16];
    float* out = (float*)d_out;

    float *x, *ksum, *perm, *smask;
    __half *qh, *kh, *vh, *skh, *svh, *hh, *oh, *mlph, *wqkv, *woh, *w1h, *w2h;
    cudaGetSymbolAddress((void**)&x, g_x);
    cudaGetSymbolAddress((void**)&qh, g_qh);
    cudaGetSymbolAddress((void**)&kh, g_kh);
    cudaGetSymbolAddress((void**)&vh, g_vh);
    cudaGetSymbolAddress((void**)&skh, g_skh);
    cudaGetSymbolAddress((void**)&svh, g_svh);
    cudaGetSymbolAddress((void**)&ksum, g_ksum);
    cudaGetSymbolAddress((void**)&perm, g_perm);
    cudaGetSymbolAddress((void**)&smask, g_smask);
    cudaGetSymbolAddress((void**)&hh, g_hh);
    cudaGetSymbolAddress((void**)&oh, g_oh);
    cudaGetSymbolAddress((void**)&mlph, g_mlph);
    cudaGetSymbolAddress((void**)&wqkv, g_wqkv);
    cudaGetSymbolAddress((void**)&woh, g_wo_h);
    cudaGetSymbolAddress((void**)&w1h, g_w1_h);
    cudaGetSymbolAddress((void**)&w2h, g_w2_h);

    cudaFuncSetAttribute(hgemm_kernel, cudaFuncAttributeMaxDynamicSharedMemorySize,
                         kSmemBytes);
    cudaFuncSetAttribute(attn_kernel, cudaFuncAttributeMaxDynamicSharedMemorySize,
                         kAttnSmem);

    int nW = kL * kD * kD;
    int nM = kL * kD * kMLP;
    {
        dim3 g(nM / 4 / 256, 6);
        wconv_kernel<<<g, 256>>>(wq, wk, wv, wo, w1, w2,
                                 wqkv, woh, w1h, w2h, nW, nM);
    }

    embed_pe_kernel<<<(kBSD + 255) / 256, 256>>>(tokens, embed, x);

    dim3 gQKV(kQKV / 128, kBS / 128);   // (12, 64)
    dim3 gD(kD / 128, kBS / 128);       // (4, 64)
    dim3 gM(kMLP / 128, kBS / 128);     // (16, 64)

    for (int l = 0; l < kL; l++) {
        __half* wqkv_l = wqkv + (size_t)l * kD * kQKV;
        __half* wo_l = woh + (size_t)l * kD * kD;
        const float* sw_l = sortw + (size_t)l * kH * kDH * kNB;
        __half* w1_l = w1h + (size_t)l * kD * kMLP;
        const float* b1_l = b1 + (size_t)l * kMLP;
        __half* w2_l = w2h + (size_t)l * kMLP * kD;
        const float* b2_l = b2 + (size_t)l * kD;

        ln_kernel<<<kBS, 128>>>(x, ln1_s + l * kD, ln1_b + l * kD, hh, nullptr);
        hgemm_kernel<<<gQKV, 256, kSmemBytes>>>(kBS, kQKV, kD, hh, wqkv_l,
                                                nullptr, nullptr, nullptr, qh, kh, vh, 0);

        ksum_kernel<<<kB * kNB, 512>>>(kh, ksum);
        sinkhorn_kernel<<<kB * kH, 256>>>(ksum, sw_l, tokens, perm, smask);
        sortmix_kernel<<<dim3(16, kH, kB), 256>>>(perm, kh, vh, skh, svh);

        attn_kernel<<<dim3(kNB, kH, kB), 256, kAttnSmem>>>(qh, kh, vh, skh, svh,
                                                           smask, tokens, oh);

        // x = x + o @ wo
        hgemm_kernel<<<gD, 256, kSmemBytes>>>(kBS, kD, kD, oh, wo_l,
                                              nullptr, x, x, nullptr, nullptr, nullptr, 2);

        // MLP
        ln_kernel<<<kBS, 128>>>(x, ln2_s + l * kD, ln2_b + l * kD, hh, nullptr);
        hgemm_kernel<<<gM, 256, kSmemBytes>>>(kBS, kMLP, kD, hh, w1_l,
                                              b1_l, nullptr, nullptr, mlph, nullptr, nullptr, 1);
        hgemm_kernel<<<gD, 256, kSmemBytes>>>(kBS, kD, kMLP, mlph, w2_l,
                                              b2_l, x, x, nullptr, nullptr, nullptr, 2);
    }

    ln_kernel<<<kBS, 128>>>(x, lnf_s, lnf_b, nullptr, out);
}